// round 3
// baseline (speedup 1.0000x reference)
#include <cuda_runtime.h>
#include <cuda_bf16.h>

#define NB 32
#define NS 1024
#define ND 256

// ---------------- scratch (static __device__, no allocation) ----------------
__device__ int   g_is64;                  // state dtype flag (1 = int64, 0 = int32)
__device__ int   g_sw_idx[NB][NS];        // switch row indices per batch
__device__ int   g_dr_idx[NB][NS];        // door column indices per batch
__device__ int   g_nsw[NB];
__device__ int   g_ndr[NB];
__device__ float g_partAll[NB][8][ND];
__device__ float g_partDoor[NB][8][ND];
__device__ float g_sumNonDoor[NB][ND];
__device__ float g_meanHalf[NB][ND];      // 0.5 * sumAll / S
__device__ float g_q[NB][NS][ND];         // q rows for switch slots
__device__ float g_kdT[NB][ND][NS];       // k for door slots, d-major (transposed)
__device__ float g_sc[NB][NS][NS];        // cw * (q . k) logits

// ---------------- K0: detect state dtype ------------------------------------
// If state is int64 (values 0..8), every odd int32 word of the buffer is 0.
// If int32, odd positions hold random 0..8 -> OR is nonzero (prob 1-(1/9)^16384).
// Scans only the first NB*NS int32 words -> no OOB under either interpretation.
__global__ void k_detect(const int* __restrict__ s32) {
    __shared__ int any;
    if (threadIdx.x == 0) any = 0;
    __syncthreads();
    int v = 0;
    for (int i = threadIdx.x; i < NB * NS / 2; i += blockDim.x)
        v |= s32[2 * i + 1];
    if (v) atomicOr(&any, 1);
    __syncthreads();
    if (threadIdx.x == 0) g_is64 = (any == 0);
}

__device__ __forceinline__ int state_at(const int* s32, int pos, int is64) {
    return is64 ? s32[2 * pos] : s32[pos];
}

// ---------------- K1: build switch/door index lists (deterministic scan) ----
__global__ void k_masks(const int* __restrict__ s32) {
    int b = blockIdx.x;
    int t = threadIdx.x;                      // 1024 threads
    int is64 = g_is64;
    int st = state_at(s32, b * NS + t, is64);
    int isw = (st == 3);
    int idr = (st == 4 || st == 5);
    unsigned mw = __ballot_sync(0xFFFFFFFFu, isw);
    unsigned md = __ballot_sync(0xFFFFFFFFu, idr);
    int lane = t & 31, w = t >> 5;
    __shared__ int cw[32], cd[32], ow[32], od[32];
    if (lane == 0) { cw[w] = __popc(mw); cd[w] = __popc(md); }
    __syncthreads();
    if (t == 0) {
        int aw = 0, ad = 0;
        for (int i = 0; i < 32; i++) {
            ow[i] = aw; aw += cw[i];
            od[i] = ad; ad += cd[i];
        }
        g_nsw[b] = aw; g_ndr[b] = ad;
    }
    __syncthreads();
    int posw = ow[w] + __popc(mw & ((1u << lane) - 1u));
    int posd = od[w] + __popc(md & ((1u << lane) - 1u));
    if (isw) g_sw_idx[b][posw] = t;
    if (idr) g_dr_idx[b][posd] = t;
}

// ---------------- K2: partial column sums over t-chunks ---------------------
__global__ void __launch_bounds__(ND) k_colsum(const float* __restrict__ emb,
                                               const int* __restrict__ s32) {
    int b = blockIdx.x, c = blockIdx.y;
    int d = threadIdx.x;
    int is64 = g_is64;
    float sa = 0.f, sd = 0.f;
    int t0 = c * 128;
    #pragma unroll 4
    for (int tt = 0; tt < 128; ++tt) {
        int t = t0 + tt;
        float v = emb[((size_t)b * NS + t) * ND + d];
        sa += v;
        int st = state_at(s32, b * NS + t, is64);
        if (st == 4 || st == 5) sd += v;
    }
    g_partAll[b][c][d]  = sa;
    g_partDoor[b][c][d] = sd;
}

// ---------------- K3: reduce partials -> sumNonDoor, meanHalf ---------------
__global__ void __launch_bounds__(ND) k_colreduce() {
    int b = blockIdx.x, d = threadIdx.x;
    float sa = 0.f, sd = 0.f;
    #pragma unroll
    for (int c = 0; c < 8; c++) { sa += g_partAll[b][c][d]; sd += g_partDoor[b][c][d]; }
    g_sumNonDoor[b][d] = sa - sd;
    g_meanHalf[b][d]   = 0.5f * sa * (1.0f / (float)NS);
}

// ---------------- K4: default output for all rows (uniform softmax) ---------
__global__ void __launch_bounds__(256) k_default(const float* __restrict__ emb,
                                                 float* __restrict__ out) {
    size_t e4 = (size_t)blockIdx.x * 256 + threadIdx.x;   // float4 index
    int b  = (int)(e4 >> 16);                             // S*D/4 = 65536 per batch
    int d4 = (int)(e4 & 63);                              // D/4 = 64
    float4 v = ((const float4*)emb)[e4];
    float4 m = ((const float4*)&g_meanHalf[b][0])[d4];
    v.x += m.x; v.y += m.y; v.z += m.z; v.w += m.w;
    ((float4*)out)[e4] = v;
}

// ---------------- K5: projections (q for switch rows, k^T for door cols) ----
// grid (8 e-tiles, B, 2).  W tile [32e x 256d] held in registers:
// thread(lane,warp) owns W[e0+lane][warp*32 .. +31].  Per row: broadcast LDS.128
// of x + FFMA only -> FFMA-pipe bound.
__global__ void __launch_bounds__(256) k_proj(const float* __restrict__ emb,
                                              const float* __restrict__ Wq,
                                              const float* __restrict__ bq,
                                              const float* __restrict__ Wk,
                                              const float* __restrict__ bk) {
    const int e0  = blockIdx.x * 32;
    const int b   = blockIdx.y;
    const int isK = blockIdx.z;
    const float* W    = isK ? Wk : Wq;
    const float* bias = isK ? bk : bq;
    const int n       = isK ? g_ndr[b] : g_nsw[b];
    const int* idx    = isK ? g_dr_idx[b] : g_sw_idx[b];
    const int tid = threadIdx.x, lane = tid & 31, w = tid >> 5;

    float4 wr[8];
    const float4* wrow = (const float4*)(W + (size_t)(e0 + lane) * ND + w * 32);
    #pragma unroll
    for (int i = 0; i < 8; i++) wr[i] = wrow[i];

    __shared__ __align__(16) float xsh[2][ND];
    __shared__ float red[2][8][32];

    for (int r0 = 0; r0 < n; r0 += 2) {
        int nr = min(2, n - r0);
        int t0 = idx[r0];
        xsh[0][tid] = emb[((size_t)b * NS + t0) * ND + tid];
        if (nr == 2) {
            int t1 = idx[r0 + 1];
            xsh[1][tid] = emb[((size_t)b * NS + t1) * ND + tid];
        }
        __syncthreads();
        float p0 = 0.f, p1 = 0.f;
        const float4* x0 = (const float4*)&xsh[0][w * 32];
        #pragma unroll
        for (int i = 0; i < 8; i++) {
            float4 a = x0[i];
            p0 += a.x * wr[i].x + a.y * wr[i].y + a.z * wr[i].z + a.w * wr[i].w;
        }
        if (nr == 2) {
            const float4* x1 = (const float4*)&xsh[1][w * 32];
            #pragma unroll
            for (int i = 0; i < 8; i++) {
                float4 a = x1[i];
                p1 += a.x * wr[i].x + a.y * wr[i].y + a.z * wr[i].z + a.w * wr[i].w;
            }
        }
        red[0][w][lane] = p0;
        red[1][w][lane] = p1;
        __syncthreads();
        if (w < nr) {   // warp 0 -> row r0, warp 1 -> row r0+1
            float s = red[w][0][lane];
            #pragma unroll
            for (int ww = 1; ww < 8; ww++) s += red[w][ww][lane];
            s += bias[e0 + lane];
            int e = e0 + lane;
            if (isK) g_kdT[b][e][r0 + w] = s;
            else     g_q[b][r0 + w][e]   = s;
        }
        __syncthreads();
    }
}

// ---------------- K6: logits  cw * (q . k)  ->  g_sc -----------------------
// grid (ceil(S/16), B).  q-tile (16 rows) transposed in smem; thread owns a
// door column j, streams kdT[d][j] (coalesced) with 4x LDS.128 broadcasts.
__global__ void __launch_bounds__(256) k_scores(const float* __restrict__ cwp) {
    const int b  = blockIdx.y;
    const int i0 = blockIdx.x * 16;
    const int nq = g_nsw[b];
    if (i0 >= nq) return;
    const int nd = g_ndr[b];
    if (nd == 0) return;
    const float cw = *cwp;
    __shared__ __align__(16) float qsh[ND][20];   // pad 20 floats (80B, 16B-aligned)
    const int tid = threadIdx.x;
    const int ni = min(16, nq - i0);
    for (int x = tid; x < 16 * ND; x += 256) {
        int i = x >> 8, e = x & 255;
        qsh[e][i] = (i < ni) ? g_q[b][i0 + i][e] : 0.f;
    }
    __syncthreads();
    for (int j = tid; j < nd; j += 256) {
        float acc[16];
        #pragma unroll
        for (int i = 0; i < 16; i++) acc[i] = 0.f;
        const float* kc = &g_kdT[b][0][j];
        #pragma unroll 4
        for (int e = 0; e < ND; e++) {
            float kv = kc[(size_t)e * NS];
            const float4* qr = (const float4*)&qsh[e][0];
            float4 q0 = qr[0], q1 = qr[1], q2 = qr[2], q3 = qr[3];
            acc[0]  += q0.x * kv; acc[1]  += q0.y * kv; acc[2]  += q0.z * kv; acc[3]  += q0.w * kv;
            acc[4]  += q1.x * kv; acc[5]  += q1.y * kv; acc[6]  += q1.z * kv; acc[7]  += q1.w * kv;
            acc[8]  += q2.x * kv; acc[9]  += q2.y * kv; acc[10] += q2.z * kv; acc[11] += q2.w * kv;
            acc[12] += q3.x * kv; acc[13] += q3.y * kv; acc[14] += q3.z * kv; acc[15] += q3.w * kv;
        }
        #pragma unroll
        for (int i = 0; i < 16; i++)
            if (i < ni) g_sc[b][i0 + i][j] = cw * acc[i];
    }
}

// ---------------- K7: stable softmax + weighted V + epilogue ----------------
// grid (ceil(S/16), B).  Per 16 switch rows: row max m (0 included iff any
// non-door col exists), per-chunk w = exp(f-m) tile in smem, V accumulation
// with thread-per-d (coalesced emb reads), then
// out = emb + 0.5 * (e^{-m} * sumNonDoor + sum_j w_j emb[t_j]) / denom.
__global__ void __launch_bounds__(256) k_attn_out(const float* __restrict__ emb,
                                                  float* __restrict__ out) {
    const int b  = blockIdx.y;
    const int i0 = blockIdx.x * 16;
    const int nq = g_nsw[b];
    if (i0 >= nq) return;
    const int nd = g_ndr[b];
    const int tid = threadIdx.x;
    const int ni = min(16, nq - i0);

    __shared__ __align__(16) float wsh[256][16];
    __shared__ int   tsh[256];
    __shared__ float msh[16], dsh[16];
    __shared__ float red[256];

    // row maxima of logits (include 0 from the non-door columns when nd<S)
    for (int i = 0; i < ni; i++) {
        float m = (nd < NS) ? 0.f : -3.0e38f;
        const float* sr = &g_sc[b][i0 + i][0];
        for (int j = tid; j < nd; j += 256) m = fmaxf(m, sr[j]);
        red[tid] = m; __syncthreads();
        #pragma unroll
        for (int s = 128; s > 0; s >>= 1) {
            if (tid < s) red[tid] = fmaxf(red[tid], red[tid + s]);
            __syncthreads();
        }
        if (tid == 0) msh[i] = red[0];
        __syncthreads();
    }

    float acc[16], dp[16];
    #pragma unroll
    for (int i = 0; i < 16; i++) { acc[i] = 0.f; dp[i] = 0.f; }

    for (int jb = 0; jb < nd; jb += 256) {
        int j = jb + tid;
        if (j < nd) {
            tsh[tid] = g_dr_idx[b][j];
            #pragma unroll
            for (int i = 0; i < 16; i++) {
                float f = (i < ni) ? __expf(g_sc[b][i0 + i][j] - msh[i]) : 0.f;
                wsh[tid][i] = f;
                dp[i] += f;
            }
        } else {
            #pragma unroll
            for (int i = 0; i < 16; i++) wsh[tid][i] = 0.f;
        }
        __syncthreads();
        int cnt = min(256, nd - jb);
        for (int jc = 0; jc < cnt; jc++) {
            float ev = emb[((size_t)b * NS + tsh[jc]) * ND + tid];
            const float4* wr = (const float4*)&wsh[jc][0];
            float4 w0 = wr[0], w1 = wr[1], w2 = wr[2], w3 = wr[3];
            acc[0]  += w0.x * ev; acc[1]  += w0.y * ev; acc[2]  += w0.z * ev; acc[3]  += w0.w * ev;
            acc[4]  += w1.x * ev; acc[5]  += w1.y * ev; acc[6]  += w1.z * ev; acc[7]  += w1.w * ev;
            acc[8]  += w2.x * ev; acc[9]  += w2.y * ev; acc[10] += w2.z * ev; acc[11] += w2.w * ev;
            acc[12] += w3.x * ev; acc[13] += w3.y * ev; acc[14] += w3.z * ev; acc[15] += w3.w * ev;
        }
        __syncthreads();
    }

    // reduce per-row exp sums
    for (int i = 0; i < ni; i++) {
        red[tid] = dp[i]; __syncthreads();
        #pragma unroll
        for (int s = 128; s > 0; s >>= 1) {
            if (tid < s) red[tid] += red[tid + s];
            __syncthreads();
        }
        if (tid == 0) dsh[i] = red[0];
        __syncthreads();
    }

    float snd = g_sumNonDoor[b][tid];
    for (int i = 0; i < ni; i++) {
        float em = __expf(-msh[i]);
        float denom = (float)(NS - nd) * em + dsh[i];
        int srow = g_sw_idx[b][i0 + i];
        size_t o = ((size_t)b * NS + srow) * ND + tid;
        out[o] = emb[o] + 0.5f * ((em * snd + acc[i]) / denom);
    }
}

// ---------------- launch -----------------------------------------------------
extern "C" void kernel_launch(void* const* d_in, const int* in_sizes, int n_in,
                              void* d_out, int out_size) {
    const float* emb   = (const float*)d_in[0];
    const int*   s32   = (const int*)d_in[1];    // state: int32 or int64, detected
    const float* Wq    = (const float*)d_in[2];
    const float* bq    = (const float*)d_in[3];
    const float* Wk    = (const float*)d_in[4];
    const float* bk    = (const float*)d_in[5];
    const float* cw    = (const float*)d_in[6];
    // d_in[7] = causal_bias: cancels inside softmax, unused.
    float* out = (float*)d_out;

    k_detect<<<1, 1024>>>(s32);
    k_masks<<<NB, NS>>>(s32);
    k_colsum<<<dim3(NB, 8), ND>>>(emb, s32);
    k_colreduce<<<NB, ND>>>();
    k_default<<<(NB * NS * (ND / 4)) / 256, 256>>>(emb, out);
    k_proj<<<dim3(8, NB, 2), 256>>>(emb, Wq, bq, Wk, bk);
    k_scores<<<dim3(NS / 16, NB), 256>>>(cw);
    k_attn_out<<<dim3(NS / 16, NB), 256>>>(emb, out);
}

// round 4
// speedup vs baseline: 2.1504x; 2.1504x over previous
#include <cuda_runtime.h>
#include <cuda_bf16.h>

#define NB 32
#define NS 1024
#define ND 256

// ---------------- scratch (static __device__, no allocation) ----------------
__device__ __align__(16) float g_M[ND][ND];     // M[d][e] = sum_a Wq[a][d]*Wk[a][e]
__device__ __align__(16) float g_vecA[ND];      // Wq^T bk
__device__ __align__(16) float g_vecB[ND];      // Wk^T bq
__device__ float g_c;                           // bq . bk
__device__ int   g_sw_idx[NB][NS];
__device__ int   g_dr_idx[NB][NS];
__device__ int   g_nsw[NB];
__device__ int   g_ndr[NB];
__device__ __align__(16) float g_partAll[NB][4][ND];
__device__ __align__(16) float g_partDoor[NB][4][ND];
__device__ __align__(16) float g_uc[NB][NS];    // cw*(x_t . vecB) per door slot
__device__ __align__(16) float g_vc[NB][NS];    // cw*(x_s . vecA + c) per switch slot
__device__ __align__(16) float g_z[NB][NS][ND]; // cw*(x_s . M) per switch slot

// ---------------- K_M: M = Wq^T Wk (32x32 tiles) + bias vectors + c ---------
__global__ void __launch_bounds__(256) k_M(const float* __restrict__ Wq,
                                           const float* __restrict__ Wk,
                                           const float* __restrict__ bq,
                                           const float* __restrict__ bk) {
    int tid = threadIdx.x;
    if (blockIdx.x == 64) {
        int d = tid;
        float va = 0.f, vb = 0.f;
        #pragma unroll 8
        for (int a = 0; a < ND; a++) {
            va += Wq[a * ND + d] * bk[a];
            vb += Wk[a * ND + d] * bq[a];
        }
        g_vecA[d] = va;
        g_vecB[d] = vb;
        if (tid < 32) {
            float c = 0.f;
            for (int i = tid; i < ND; i += 32) c += bq[i] * bk[i];
            #pragma unroll
            for (int o = 16; o; o >>= 1) c += __shfl_down_sync(0xFFFFFFFFu, c, o);
            if (tid == 0) g_c = c;
        }
        return;
    }
    int dt = blockIdx.x >> 3, et = blockIdx.x & 7;
    __shared__ float As[16][32], Bs[16][32];
    float a00 = 0.f, a01 = 0.f, a10 = 0.f, a11 = 0.f;
    int dg = tid >> 4, eg = tid & 15;
    int al = tid >> 4, c2 = (tid & 15) * 2;
    for (int a0 = 0; a0 < ND; a0 += 16) {
        *(float2*)&As[al][c2] = *(const float2*)&Wq[(a0 + al) * ND + dt * 32 + c2];
        *(float2*)&Bs[al][c2] = *(const float2*)&Wk[(a0 + al) * ND + et * 32 + c2];
        __syncthreads();
        #pragma unroll
        for (int k = 0; k < 16; k++) {
            float2 av = *(const float2*)&As[k][dg * 2];
            float2 bv = *(const float2*)&Bs[k][eg * 2];
            a00 += av.x * bv.x; a01 += av.x * bv.y;
            a10 += av.y * bv.x; a11 += av.y * bv.y;
        }
        __syncthreads();
    }
    int d = dt * 32 + dg * 2, e = et * 32 + eg * 2;
    g_M[d][e]     = a00; g_M[d][e + 1]     = a01;
    g_M[d + 1][e] = a10; g_M[d + 1][e + 1] = a11;
}

// ---------------- K_prep: dtype detect + masks + bias dots | colsum ---------
__global__ void __launch_bounds__(1024) k_prep(const int* __restrict__ s32,
                                               const float* __restrict__ emb,
                                               const float* __restrict__ cwp) {
    int b = blockIdx.x, bz = blockIdx.y, tid = threadIdx.x;
    // int64 vs int32: odd int32 words in [b*NS,(b+1)*NS) are all 0 iff int64.
    int vdet = (tid < 512) ? s32[b * NS + 2 * tid + 1] : 0;
    int is64 = !__syncthreads_or(vdet != 0);

    if (bz == 0) {
        int t = tid;
        int st = is64 ? s32[2 * (b * NS + t)] : s32[b * NS + t];
        int isw = (st == 3), idr = (st == 4 || st == 5);
        unsigned mw = __ballot_sync(0xFFFFFFFFu, isw);
        unsigned md = __ballot_sync(0xFFFFFFFFu, idr);
        int lane = t & 31, w = t >> 5;
        __shared__ int cw_[32], cd_[32], ow_[32], od_[32], snsw, sndr;
        if (lane == 0) { cw_[w] = __popc(mw); cd_[w] = __popc(md); }
        __syncthreads();
        if (tid == 0) {
            int aw = 0, ad = 0;
            for (int i = 0; i < 32; i++) {
                ow_[i] = aw; aw += cw_[i];
                od_[i] = ad; ad += cd_[i];
            }
            g_nsw[b] = aw; g_ndr[b] = ad; snsw = aw; sndr = ad;
        }
        __syncthreads();
        if (isw) g_sw_idx[b][ow_[w] + __popc(mw & ((1u << lane) - 1u))] = t;
        if (idr) g_dr_idx[b][od_[w] + __popc(md & ((1u << lane) - 1u))] = t;
        __syncthreads();
        float cwv = *cwp, cval = g_c;
        int nd = sndr, nw2 = snsw;
        for (int slot = w; slot < nd; slot += 32) {
            int tt = g_dr_idx[b][slot];
            const float4* er = (const float4*)&emb[((size_t)b * NS + tt) * ND];
            const float4* vr = (const float4*)g_vecB;
            float s = 0.f;
            #pragma unroll
            for (int j2 = 0; j2 < 2; j2++) {
                float4 e4 = er[lane + 32 * j2], v4 = vr[lane + 32 * j2];
                s += e4.x * v4.x + e4.y * v4.y + e4.z * v4.z + e4.w * v4.w;
            }
            #pragma unroll
            for (int o = 16; o; o >>= 1) s += __shfl_down_sync(0xFFFFFFFFu, s, o);
            if (lane == 0) g_uc[b][slot] = cwv * s;
        }
        for (int slot = w; slot < nw2; slot += 32) {
            int tt = g_sw_idx[b][slot];
            const float4* er = (const float4*)&emb[((size_t)b * NS + tt) * ND];
            const float4* vr = (const float4*)g_vecA;
            float s = 0.f;
            #pragma unroll
            for (int j2 = 0; j2 < 2; j2++) {
                float4 e4 = er[lane + 32 * j2], v4 = vr[lane + 32 * j2];
                s += e4.x * v4.x + e4.y * v4.y + e4.z * v4.z + e4.w * v4.w;
            }
            #pragma unroll
            for (int o = 16; o; o >>= 1) s += __shfl_down_sync(0xFFFFFFFFu, s, o);
            if (lane == 0) g_vc[b][slot] = cwv * (s + cval);
        }
    } else {
        int c = bz - 1, tg = tid >> 8, d = tid & 255;
        float sa = 0.f, sd = 0.f;
        int tb = c * 256 + tg * 64;
        #pragma unroll 4
        for (int i = 0; i < 64; i++) {
            int t = tb + i;
            float v = emb[((size_t)b * NS + t) * ND + d];
            int st = is64 ? s32[2 * (b * NS + t)] : s32[b * NS + t];
            sa += v;
            if (st == 4 || st == 5) sd += v;
        }
        __shared__ float psA[4][ND], psD[4][ND];
        psA[tg][d] = sa; psD[tg][d] = sd;
        __syncthreads();
        if (tid < ND) {
            float a = 0.f, dd = 0.f;
            #pragma unroll
            for (int g = 0; g < 4; g++) { a += psA[g][tid]; dd += psD[g][tid]; }
            g_partAll[b][c][tid]  = a;
            g_partDoor[b][c][tid] = dd;
        }
    }
}

// ---------------- K_default: out = emb + 0.5*colMean (all rows) -------------
__global__ void __launch_bounds__(256) k_default(const float* __restrict__ emb,
                                                 float* __restrict__ out) {
    size_t e4 = (size_t)blockIdx.x * 256 + threadIdx.x;
    int b  = (int)(e4 >> 16);
    int d4 = (int)(e4 & 63);
    float4 p0 = ((const float4*)g_partAll[b][0])[d4];
    float4 p1 = ((const float4*)g_partAll[b][1])[d4];
    float4 p2 = ((const float4*)g_partAll[b][2])[d4];
    float4 p3 = ((const float4*)g_partAll[b][3])[d4];
    const float kk = 0.5f / 1024.f;
    float4 v = ((const float4*)emb)[e4];
    v.x += (p0.x + p1.x + p2.x + p3.x) * kk;
    v.y += (p0.y + p1.y + p2.y + p3.y) * kk;
    v.z += (p0.z + p1.z + p2.z + p3.z) * kk;
    v.w += (p0.w + p1.w + p2.w + p3.w) * kk;
    ((float4*)out)[e4] = v;
}

// ---------------- K_z: z = cw * X_switch . M, 64x64 tiles, K=256 ------------
__global__ void __launch_bounds__(256) k_z(const float* __restrict__ emb,
                                           const float* __restrict__ cwp) {
    int et = blockIdx.x, b = blockIdx.y, mt = blockIdx.z;
    int nsw = g_nsw[b];
    if (mt * 64 >= nsw) return;
    int tid = threadIdx.x;
    __shared__ float Xs[16][68];
    __shared__ float Ms[16][68];
    __shared__ const float* rp[64];
    if (tid < 64) {
        int slot = mt * 64 + tid;
        int t = g_sw_idx[b][(slot < nsw) ? slot : 0];
        rp[tid] = emb + ((size_t)b * NS + t) * ND;
    }
    __syncthreads();
    float acc[4][4] = {};
    const int row = tid >> 2, kc = (tid & 3) * 4;
    const int rg = tid >> 4, eg = tid & 15;
    const int mk = tid >> 4, me4 = (tid & 15) * 4;
    const float* xp = rp[row];
    for (int k0 = 0; k0 < ND; k0 += 16) {
        float4 xv = *(const float4*)(xp + k0 + kc);
        float4 mv = *(const float4*)&g_M[k0 + mk][et * 64 + me4];
        __syncthreads();
        Xs[kc + 0][row] = xv.x; Xs[kc + 1][row] = xv.y;
        Xs[kc + 2][row] = xv.z; Xs[kc + 3][row] = xv.w;
        *(float4*)&Ms[mk][me4] = mv;
        __syncthreads();
        #pragma unroll
        for (int k = 0; k < 16; k++) {
            float4 xf = *(const float4*)&Xs[k][rg * 4];
            float4 mf = *(const float4*)&Ms[k][eg * 4];
            acc[0][0] += xf.x * mf.x; acc[0][1] += xf.x * mf.y; acc[0][2] += xf.x * mf.z; acc[0][3] += xf.x * mf.w;
            acc[1][0] += xf.y * mf.x; acc[1][1] += xf.y * mf.y; acc[1][2] += xf.y * mf.z; acc[1][3] += xf.y * mf.w;
            acc[2][0] += xf.z * mf.x; acc[2][1] += xf.z * mf.y; acc[2][2] += xf.z * mf.z; acc[2][3] += xf.z * mf.w;
            acc[3][0] += xf.w * mf.x; acc[3][1] += xf.w * mf.y; acc[3][2] += xf.w * mf.z; acc[3][3] += xf.w * mf.w;
        }
    }
    float cwv = *cwp;
    #pragma unroll
    for (int i = 0; i < 4; i++) {
        int slot = mt * 64 + rg * 4 + i;
        if (slot < nsw) {
            float4 o = make_float4(cwv * acc[i][0], cwv * acc[i][1],
                                   cwv * acc[i][2], cwv * acc[i][3]);
            *(float4*)&g_z[b][slot][et * 64 + eg * 4] = o;
        }
    }
}

// ---------------- K_attn: fused scores + online softmax + V + epilogue ------
struct AttnSmem {
    float Esh[64][260];   // door-row emb tile (pad 260: conflict-free both loops)
    float zsh[16][260];   // z rows for this i-tile
    float ssh[64][20];    // scores -> softmax weights (in place)
    float red[16][16];
    float uch[64];
    int   tj[64];
    float vch[16];
    float m[16];
    float dsum[16];
    float scale[16];
};

__global__ void __launch_bounds__(256) k_attn(const float* __restrict__ emb,
                                              float* __restrict__ out) {
    extern __shared__ char smraw[];
    AttnSmem* S = (AttnSmem*)smraw;
    int mt = blockIdx.x, b = blockIdx.y;
    int nsw = g_nsw[b];
    int i0 = mt * 16;
    if (i0 >= nsw) return;
    int nd = g_ndr[b];
    int tid = threadIdx.x;
    int ni = min(16, nsw - i0);

    for (int idx = tid; idx < 16 * ND; idx += 256) {
        int i = idx >> 8, e = idx & 255;
        S->zsh[i][e] = (i < ni) ? g_z[b][i0 + i][e] : 0.f;
    }
    if (tid < 16) {
        S->vch[tid]  = (tid < ni) ? g_vc[b][i0 + tid] : -1e30f;
        S->m[tid]    = (nd < NS) ? 0.f : -1e30f;
        S->dsum[tid] = 0.f;
    }
    float acc[16];
    #pragma unroll
    for (int i = 0; i < 16; i++) acc[i] = 0.f;

    const int il = tid & 15, jg = tid >> 4;

    for (int jb = 0; jb < nd; jb += 64) {
        int cnt = min(64, nd - jb);
        __syncthreads();
        if (tid < 64) {
            S->tj[tid]  = g_dr_idx[b][(tid < cnt) ? (jb + tid) : jb];
            S->uch[tid] = (tid < cnt) ? g_uc[b][jb + tid] : 0.f;
        }
        __syncthreads();
        for (int idx = tid; idx < 64 * 64; idx += 256) {
            int j = idx >> 6, q = idx & 63;
            float4 v = ((const float4*)&emb[((size_t)b * NS + S->tj[j]) * ND])[q];
            *(float4*)&S->Esh[j][q * 4] = v;
        }
        __syncthreads();
        // ---- scores: thread (il, jg) computes s[il][jg*4+q]
        {
            float s0 = 0.f, s1 = 0.f, s2 = 0.f, s3 = 0.f;
            #pragma unroll 4
            for (int e = 0; e < ND; e += 4) {
                float4 zf = *(const float4*)&S->zsh[il][e];
                float4 e0 = *(const float4*)&S->Esh[jg * 4 + 0][e];
                float4 e1 = *(const float4*)&S->Esh[jg * 4 + 1][e];
                float4 e2 = *(const float4*)&S->Esh[jg * 4 + 2][e];
                float4 e3 = *(const float4*)&S->Esh[jg * 4 + 3][e];
                s0 += zf.x * e0.x + zf.y * e0.y + zf.z * e0.z + zf.w * e0.w;
                s1 += zf.x * e1.x + zf.y * e1.y + zf.z * e1.z + zf.w * e1.w;
                s2 += zf.x * e2.x + zf.y * e2.y + zf.z * e2.z + zf.w * e2.w;
                s3 += zf.x * e3.x + zf.y * e3.y + zf.z * e3.z + zf.w * e3.w;
            }
            float vci = S->vch[il];
            int j0 = jg * 4;
            S->ssh[j0 + 0][il] = (j0 + 0 < cnt) ? s0 + vci + S->uch[j0 + 0] : -1e30f;
            S->ssh[j0 + 1][il] = (j0 + 1 < cnt) ? s1 + vci + S->uch[j0 + 1] : -1e30f;
            S->ssh[j0 + 2][il] = (j0 + 2 < cnt) ? s2 + vci + S->uch[j0 + 2] : -1e30f;
            S->ssh[j0 + 3][il] = (j0 + 3 < cnt) ? s3 + vci + S->uch[j0 + 3] : -1e30f;
        }
        __syncthreads();
        if (tid < 16) {
            float mo = S->m[tid], mn = mo;
            #pragma unroll 8
            for (int j = 0; j < 64; j++) mn = fmaxf(mn, S->ssh[j][tid]);
            S->scale[tid] = __expf(mo - mn);
            S->m[tid] = mn;
        }
        __syncthreads();
        {
            float mi = S->m[il];
            float ls = 0.f;
            #pragma unroll
            for (int q = 0; q < 4; q++) {
                int j = jg * 4 + q;
                float w = __expf(S->ssh[j][il] - mi);
                S->ssh[j][il] = w;
                ls += w;
            }
            S->red[jg][il] = ls;
        }
        __syncthreads();
        if (tid < 16) {
            float cs = 0.f;
            #pragma unroll
            for (int g = 0; g < 16; g++) cs += S->red[g][tid];
            S->dsum[tid] = S->dsum[tid] * S->scale[tid] + cs;
        }
        // ---- V accumulate: thread = d
        #pragma unroll
        for (int i = 0; i < 16; i++) acc[i] *= S->scale[i];
        #pragma unroll 2
        for (int j = 0; j < 64; j++) {
            float ev = S->Esh[j][tid];
            float4 w0 = *(const float4*)&S->ssh[j][0];
            float4 w1 = *(const float4*)&S->ssh[j][4];
            float4 w2 = *(const float4*)&S->ssh[j][8];
            float4 w3 = *(const float4*)&S->ssh[j][12];
            acc[0]  += w0.x * ev; acc[1]  += w0.y * ev; acc[2]  += w0.z * ev; acc[3]  += w0.w * ev;
            acc[4]  += w1.x * ev; acc[5]  += w1.y * ev; acc[6]  += w1.z * ev; acc[7]  += w1.w * ev;
            acc[8]  += w2.x * ev; acc[9]  += w2.y * ev; acc[10] += w2.z * ev; acc[11] += w2.w * ev;
            acc[12] += w3.x * ev; acc[13] += w3.y * ev; acc[14] += w3.z * ev; acc[15] += w3.w * ev;
        }
    }
    __syncthreads();
    float sndv = 0.f;
    #pragma unroll
    for (int c = 0; c < 4; c++) sndv += g_partAll[b][c][tid] - g_partDoor[b][c][tid];
    for (int i = 0; i < ni; i++) {
        float em = __expf(-S->m[i]);
        float denom = (float)(NS - nd) * em + S->dsum[i];
        int srow = g_sw_idx[b][i0 + i];
        size_t o = ((size_t)b * NS + srow) * ND + tid;
        out[o] = emb[o] + 0.5f * ((em * sndv + acc[i]) / denom);
    }
}

// ---------------- launch ------------------------------------------------------
extern "C" void kernel_launch(void* const* d_in, const int* in_sizes, int n_in,
                              void* d_out, int out_size) {
    const float* emb = (const float*)d_in[0];
    const int*   s32 = (const int*)d_in[1];   // int32 or int64, detected per block
    const float* Wq  = (const float*)d_in[2];
    const float* bq  = (const float*)d_in[3];
    const float* Wk  = (const float*)d_in[4];
    const float* bk  = (const float*)d_in[5];
    const float* cw  = (const float*)d_in[6];
    // d_in[7] = causal_bias: cancels inside softmax, unused.
    float* out = (float*)d_out;

    cudaFuncSetAttribute(k_attn, cudaFuncAttributeMaxDynamicSharedMemorySize,
                         (int)sizeof(AttnSmem));

    k_M<<<65, 256>>>(Wq, Wk, bq, bk);
    k_prep<<<dim3(NB, 5), 1024>>>(s32, emb, cw);
    k_default<<<(NB * NS * (ND / 4)) / 256, 256>>>(emb, out);
    k_z<<<dim3(4, NB, 16), 256>>>(emb, cw);
    k_attn<<<dim3(64, NB), 256, sizeof(AttnSmem)>>>(emb, out);
}